// round 15
// baseline (speedup 1.0000x reference)
#include <cuda_runtime.h>
#include <cuda_bf16.h>
#include <math.h>
#include <cstdint>

// Problem sizes (fixed by the reference)
#define TT 512
#define BB 128
#define HH 512
#define H3 1536
#define KP 1536   // GI split-K' = 3*HH

// ---------------- scratch (static __device__, no allocs) ----------------
__device__ float g_GI[TT * BB * H3];                  // x@Wi + bi (fp32)
__device__ __nv_bfloat16 g_A2[(size_t)TT * BB * KP];  // A' = [x_hi | x_lo | x_hi]
__device__ __nv_bfloat16 g_WT[(size_t)H3 * KP];       // Wi'^T for GI GEMM
__device__ __nv_bfloat16 g_Hbf[2 * BB * 1024];        // h state: [buf][b][lo_s 0..511 | hi 512..1023]
__device__ __nv_bfloat16 g_Wbf[(size_t)H3 * 1024];    // Wh rows: [gc][Whi 0..511 | Wlo_s 512..1023]
__device__ float g_RS[(TT + 1) * BB];                 // keep multipliers (0 = reset)
__device__ int   g_reset_mode;
__device__ unsigned int g_flag[4][32];                // per-CTA arrival flags (value = t+1)

// ---------------- small PTX helpers ----------------
__device__ __forceinline__ void cp16(void* dst, const void* src) {
    unsigned s = (unsigned)__cvta_generic_to_shared(dst);
    asm volatile("cp.async.cg.shared.global [%0], [%1], 16;" :: "r"(s), "l"(src));
}
__device__ __forceinline__ uint32_t smem_u32(const void* p) {
    return (uint32_t)__cvta_generic_to_shared(p);
}
__device__ __forceinline__ void ldsm_x4(uint32_t& r0, uint32_t& r1,
                                        uint32_t& r2, uint32_t& r3, uint32_t addr) {
    asm volatile("ldmatrix.sync.aligned.m8n8.x4.shared.b16 {%0,%1,%2,%3}, [%4];"
                 : "=r"(r0), "=r"(r1), "=r"(r2), "=r"(r3) : "r"(addr));
}
__device__ __forceinline__ void mma_bf16(float* d, const uint32_t* a,
                                         uint32_t b0, uint32_t b1) {
    asm volatile("mma.sync.aligned.m16n8k16.row.col.f32.bf16.bf16.f32 "
                 "{%0,%1,%2,%3}, {%4,%5,%6,%7}, {%8,%9}, {%0,%1,%2,%3};"
                 : "+f"(d[0]), "+f"(d[1]), "+f"(d[2]), "+f"(d[3])
                 : "r"(a[0]), "r"(a[1]), "r"(a[2]), "r"(a[3]), "r"(b0), "r"(b1));
}
// fast activations: ex2.approx/rcp.approx (rel err ~2^-22), clamped
__device__ __forceinline__ float fsigmoid(float x) {
    x = fminf(30.f, fmaxf(-30.f, x));
    float e;
    asm("ex2.approx.f32 %0, %1;" : "=f"(e) : "f"(-1.4426950408889634f * x));
    float r;
    asm("rcp.approx.f32 %0, %1;" : "=f"(r) : "f"(1.0f + e));
    return r;
}
__device__ __forceinline__ float ftanh_fast(float x) {
    x = fminf(30.f, fmaxf(-30.f, x));
    float e;
    asm("ex2.approx.f32 %0, %1;" : "=f"(e) : "f"(-2.8853900817779268f * x));
    float r;
    asm("rcp.approx.f32 %0, %1;" : "=f"(r) : "f"(1.0f + e));
    return (1.0f - e) * r;
}

// ---------------- detect how the harness stored the bool resets ----------
__global__ void detect_reset_mode_kernel(const unsigned char* __restrict__ r) {
    __shared__ int cnt[4];
    if (threadIdx.x < 4) cnt[threadIdx.x] = 0;
    __syncthreads();
    int local[4] = {0, 0, 0, 0};
    const uchar4* r4 = (const uchar4*)r;
    for (int i = threadIdx.x; i < (TT * BB) / 4; i += blockDim.x) {
        uchar4 v = r4[i];
        local[0] += (v.x != 0); local[1] += (v.y != 0);
        local[2] += (v.z != 0); local[3] += (v.w != 0);
    }
#pragma unroll
    for (int q = 0; q < 4; ++q) atomicAdd(&cnt[q], local[q]);
    __syncthreads();
    if (threadIdx.x == 0) {
        int mode;
        if (cnt[1] > 0) mode = 1;
        else if (cnt[0] > 0) mode = 0;
        else if (cnt[2] > 0 || cnt[3] > 0) mode = 2;
        else mode = 0;
        g_reset_mode = mode;
    }
}

__global__ void expand_resets_kernel(const void* __restrict__ resets) {
    int i = blockIdx.x * blockDim.x + threadIdx.x;
    if (i >= (TT + 1) * BB) return;
    if (i >= TT * BB) { g_RS[i] = 1.0f; return; }
    const int mode = g_reset_mode;
    bool rst;
    if (mode == 0)      rst = ((const int*)resets)[i] != 0;
    else if (mode == 1) rst = ((const unsigned char*)resets)[i] != 0;
    else                rst = ((const float*)resets)[i] != 0.0f;
    g_RS[i] = rst ? 0.0f : 1.0f;
}

// init: flags + h0 (reset-applied, bf16 hi/lo split, [b][k'] layout)
__global__ void init_kernel(const float* __restrict__ h0) {
    int i = blockIdx.x * blockDim.x + threadIdx.x;
    if (i < 128) g_flag[i >> 5][i & 31] = 0u;
    if (i < BB * HH) {
        int b = i >> 9;
        int j = i & (HH - 1);
        float h = h0[i] * g_RS[b];
        __nv_bfloat16 hi = __float2bfloat16(h);
        __nv_bfloat16 lo = __float2bfloat16((h - __bfloat162float(hi)) * 256.0f);
        g_Hbf[b * 1024 + j] = lo;
        g_Hbf[b * 1024 + 512 + j] = hi;
    }
}

// ---------------- split-fp32 -> bf16 conversion kernels ----------------
__global__ void convert_x_kernel(const float* __restrict__ x) {
    const int n = TT * BB * HH;
    for (int idx = blockIdx.x * blockDim.x + threadIdx.x; idx < n;
         idx += gridDim.x * blockDim.x) {
        int m = idx >> 9, k = idx & 511;
        float v = x[idx];
        __nv_bfloat16 hi = __float2bfloat16(v);
        __nv_bfloat16 lo = __float2bfloat16(v - __bfloat162float(hi));
        size_t base = (size_t)m * KP;
        g_A2[base + k] = hi;
        g_A2[base + 512 + k] = lo;
        g_A2[base + 1024 + k] = hi;
    }
}
__global__ void convert_w_kernel(const float* __restrict__ Wi) {
    const int n = HH * H3;
    for (int idx = blockIdx.x * blockDim.x + threadIdx.x; idx < n;
         idx += gridDim.x * blockDim.x) {
        int k = idx / H3, c = idx % H3;          // Wi[k][c]
        float v = Wi[idx];
        __nv_bfloat16 hi = __float2bfloat16(v);
        __nv_bfloat16 lo = __float2bfloat16(v - __bfloat162float(hi));
        size_t base = (size_t)c * KP;
        g_WT[base + k] = hi;
        g_WT[base + 512 + k] = hi;
        g_WT[base + 1024 + k] = lo;
    }
}
// Wh -> g_Wbf rows: [gc][Whi(k) 0..511 | Wlo_s(k) 512..1023]
__global__ void convert_wh_kernel(const float* __restrict__ Wh) {
    const int n = HH * H3;
    for (int idx = blockIdx.x * blockDim.x + threadIdx.x; idx < n;
         idx += gridDim.x * blockDim.x) {
        int gc = idx >> 9, k = idx & 511;
        float v = Wh[(size_t)k * H3 + gc];
        __nv_bfloat16 hi = __float2bfloat16(v);
        __nv_bfloat16 lo = __float2bfloat16((v - __bfloat162float(hi)) * 256.0f);
        g_Wbf[(size_t)gc * 1024 + k] = hi;
        g_Wbf[(size_t)gc * 1024 + 512 + k] = lo;
    }
}

// ---------------- GI GEMM via mma.sync bf16 (HMMA) -----------------------
#define HBM_M 128
#define HBM_N 128
#define HBM_K 32
#define APITCH 40
#define STAGE_BYTES 20480
#define NSTAGE 3
#define HB_BIAS_OFF (NSTAGE * STAGE_BYTES)
#define HB_SMEM_BYTES (HB_BIAS_OFF + 512)
#define NC (KP / HBM_K)

extern __shared__ float smf[];

__device__ __forceinline__ void hmma_stage(char* smc, int slot, int kc,
                                           const __nv_bfloat16* Ag,
                                           const __nv_bfloat16* Bg, int tid) {
    char* sA = smc + slot * STAGE_BYTES;
    char* sB = sA + 10240;
    const int k0 = kc * HBM_K;
#pragma unroll
    for (int i = 0; i < 2; ++i) {
        int id = tid * 2 + i;
        int row = id >> 2, seg = id & 3;
        cp16(sA + row * 80 + seg * 16, Ag + (size_t)row * KP + k0 + seg * 8);
        cp16(sB + row * 80 + seg * 16, Bg + (size_t)row * KP + k0 + seg * 8);
    }
}

__global__ __launch_bounds__(256) void gi_hmma_kernel(const float* __restrict__ bias) {
    char* smc = (char*)smf;
    const uint32_t sbase = smem_u32(smc);
    const int tid = threadIdx.x;
    const int lane = tid & 31, warp = tid >> 5;
    const int wm = warp >> 1, wn = warp & 1;

    const int bid = blockIdx.x;
    const int grp = bid / 96, r = bid % 96;
    const int ntile = r % 12, mtile = grp * 8 + r / 12;
    const int m0 = mtile * HBM_M, n0 = ntile * HBM_N;
    const __nv_bfloat16* Ag = g_A2 + (size_t)m0 * KP;
    const __nv_bfloat16* Bg = g_WT + (size_t)n0 * KP;

    float* bsm = (float*)(smc + HB_BIAS_OFF);
    if (tid < 128) bsm[tid] = bias[n0 + tid];

    float acc[2][8][4];
#pragma unroll
    for (int mt = 0; mt < 2; ++mt)
#pragma unroll
        for (int nt = 0; nt < 8; ++nt)
#pragma unroll
            for (int q = 0; q < 4; ++q) acc[mt][nt][q] = 0.f;

    hmma_stage(smc, 0, 0, Ag, Bg, tid);
    asm volatile("cp.async.commit_group;");
    hmma_stage(smc, 1, 1, Ag, Bg, tid);
    asm volatile("cp.async.commit_group;");

    const int lrow = lane & 15;
    const int lcol8 = (lane >> 4) * 8;

    for (int c = 0; c < NC; ++c) {
        if (c == NC - 1) asm volatile("cp.async.wait_group 0;");
        else             asm volatile("cp.async.wait_group 1;");
        __syncthreads();
        if (c + 2 < NC) {
            hmma_stage(smc, (c + 2) % NSTAGE, c + 2, Ag, Bg, tid);
            asm volatile("cp.async.commit_group;");
        }

        const uint32_t aBase = sbase + (uint32_t)(c % NSTAGE) * STAGE_BYTES;
        const uint32_t bBase = aBase + 10240;

#pragma unroll
        for (int ks = 0; ks < 2; ++ks) {
            const int col = ks * 16 + lcol8;
            uint32_t af[2][4];
#pragma unroll
            for (int mt = 0; mt < 2; ++mt) {
                uint32_t addr = aBase +
                    (uint32_t)((wm * 32 + mt * 16 + lrow) * APITCH + col) * 2;
                ldsm_x4(af[mt][0], af[mt][1], af[mt][2], af[mt][3], addr);
            }
            uint32_t bf[4][4];
#pragma unroll
            for (int ng = 0; ng < 4; ++ng) {
                uint32_t addr = bBase +
                    (uint32_t)((wn * 64 + ng * 16 + lrow) * APITCH + col) * 2;
                ldsm_x4(bf[ng][0], bf[ng][1], bf[ng][2], bf[ng][3], addr);
            }
#pragma unroll
            for (int mt = 0; mt < 2; ++mt)
#pragma unroll
                for (int ng = 0; ng < 4; ++ng) {
                    mma_bf16(acc[mt][ng * 2 + 0], af[mt], bf[ng][0], bf[ng][2]);
                    mma_bf16(acc[mt][ng * 2 + 1], af[mt], bf[ng][1], bf[ng][3]);
                }
        }
        __syncthreads();
    }

    const int ml = lane >> 2;
    const int nl = (lane & 3) * 2;
#pragma unroll
    for (int mt = 0; mt < 2; ++mt) {
        const int mg = m0 + wm * 32 + mt * 16 + ml;
#pragma unroll
        for (int nt = 0; nt < 8; ++nt) {
            const int ncol = wn * 64 + nt * 8 + nl;
            const float b0 = bsm[ncol], b1 = bsm[ncol + 1];
            float2 v0, v1;
            v0.x = acc[mt][nt][0] + b0; v0.y = acc[mt][nt][1] + b1;
            v1.x = acc[mt][nt][2] + b0; v1.y = acc[mt][nt][3] + b1;
            *(float2*)(g_GI + (size_t)mg * H3 + n0 + ncol) = v0;
            *(float2*)(g_GI + (size_t)(mg + 8) * H3 + n0 + ncol) = v1;
        }
    }
}

// ---------------- persistent scan kernel: h@Wh via HMMA, pipelined -------
#define NCTA 128
#define SCAN_THREADS 128
#define ROWB 2064     // bytes per smem row (2048 data + 16 pad)
#define SW_OFF   0
#define SA_OFF   99072                       // 48*2064
#define SGI_OFF  (99072 + 66048)             // = 165120
#define SRED_OFF (165120 + 12288)            // = 177408
#define SCAN_SMEM_BYTES (177408 + 26624)     // = 204032

__global__ __launch_bounds__(SCAN_THREADS, 1) void scan_kernel(
    const float* __restrict__ bhn,             // [H]
    float* __restrict__ out)                   // [T,B,H]
{
    char* smc = (char*)smf;
    char* sW  = smc + SW_OFF;                  // 48 rows x 2064B: [c][Whi|Wlo_s]
    char* sA  = smc + SA_OFF;                  // 32 rows x 2064B: [b][lo_s|hi]
    float* sGI  = (float*)(smc + SGI_OFF);     // [2][3][32][16]
    float* sRed = (float*)(smc + SRED_OFF);    // [4][32][52]
    const uint32_t sWu = smem_u32(sW);
    const uint32_t sAu = smem_u32(sA);

    const int tid  = threadIdx.x;
    const int lane = tid & 31;
    const int wid  = tid >> 5;
    const int ji   = blockIdx.x & 31;          // CTA index within b-group
    const int bi   = blockIdx.x >> 5;          // b-group
    const int jbase = ji * 16;
    const int bbase = bi * 32;
    const int eb = tid & 31;
    const int jq = tid >> 5;

    // stage weights once: 48 rows of 2048B
    for (int p = tid; p < 48 * 128; p += SCAN_THREADS) {
        int row = p >> 7, seg = p & 127;
        int gc = (row % 3) * HH + jbase + row / 3;   // c = jl*3+g -> gc
        cp16(sW + row * ROWB + seg * 16, g_Wbf + (size_t)gc * 1024 + seg * 8);
    }
    // prefetch gi for t=0 into buffer 0
#pragma unroll
    for (int q = 0; q < 3; ++q) {
        int p = tid + q * SCAN_THREADS;
        int g = p >> 7, rem = p & 127;
        int b = rem >> 2, j4 = rem & 3;
        cp16(sGI + (g * 32 + b) * 16 + j4 * 4,
             g_GI + (size_t)(bbase + b) * H3 + g * HH + jbase + j4 * 4);
    }
    asm volatile("cp.async.commit_group;");
    asm volatile("cp.async.wait_group 0;");
    __syncthreads();                            // weights + gi(0) visible

    float bhn_j[4];
#pragma unroll
    for (int ii = 0; ii < 4; ++ii) bhn_j[ii] = bhn[jbase + jq * 4 + ii];

    const int lrow = lane & 15;
    const int lcol8 = (lane >> 4) * 8;

    for (int t = 0; t < TT; ++t) {
        const __nv_bfloat16* hsrc = g_Hbf + (t & 1) * BB * 1024;
        __nv_bfloat16* hdst       = g_Hbf + ((t + 1) & 1) * BB * 1024;

        // Warp w stages ONLY its own acc2 chunk (byte cols [512w, 512w+512))
        // in 4 sub-chunks of 128B cols, one commit each (barrier-free use).
        {
            const char* srcb = (const char*)hsrc + (size_t)bbase * 2048 + wid * 512;
            char* dstb = sA + wid * 512;
#pragma unroll
            for (int s = 0; s < 4; ++s) {
#pragma unroll
                for (int q = 0; q < 8; ++q) {
                    int p = lane + q * 32;       // 0..255
                    int row = p >> 3, sc = p & 7;
                    cp16(dstb + row * ROWB + s * 128 + sc * 16,
                         srcb + row * 2048 + s * 128 + sc * 16);
                }
                asm volatile("cp.async.commit_group;");
            }
        }
        // retire the gi prefetch group (no-op at t=0)
        asm volatile("cp.async.wait_group 4;");

        float acc1[2][6][4], acc2[2][6][4];
#pragma unroll
        for (int mt = 0; mt < 2; ++mt)
#pragma unroll
            for (int nt = 0; nt < 6; ++nt)
#pragma unroll
                for (int q = 0; q < 4; ++q) { acc1[mt][nt][q] = 0.f; acc2[mt][nt][q] = 0.f; }

        // acc2 pass pipelined over sub-chunks: [lo_s | hi] @ [Whi ; Wlo_s]
#pragma unroll
        for (int s = 0; s < 4; ++s) {
            if (s == 0)      asm volatile("cp.async.wait_group 3;");
            else if (s == 1) asm volatile("cp.async.wait_group 2;");
            else if (s == 2) asm volatile("cp.async.wait_group 1;");
            else             asm volatile("cp.async.wait_group 0;");
#pragma unroll
            for (int i = 0; i < 4; ++i) {
                const int ks = s * 4 + i;
                const int col = wid * 256 + ks * 16 + lcol8;
                uint32_t af[2][4];
#pragma unroll
                for (int mt = 0; mt < 2; ++mt)
                    ldsm_x4(af[mt][0], af[mt][1], af[mt][2], af[mt][3],
                            sAu + (uint32_t)(mt * 16 + lrow) * ROWB + col * 2);
                uint32_t bf[3][4];
#pragma unroll
                for (int ng = 0; ng < 3; ++ng)
                    ldsm_x4(bf[ng][0], bf[ng][1], bf[ng][2], bf[ng][3],
                            sWu + (uint32_t)(ng * 16 + lrow) * ROWB + col * 2);
#pragma unroll
                for (int mt = 0; mt < 2; ++mt)
#pragma unroll
                    for (int ng = 0; ng < 3; ++ng) {
                        mma_bf16(acc2[mt][ng * 2 + 0], af[mt], bf[ng][0], bf[ng][2]);
                        mma_bf16(acc2[mt][ng * 2 + 1], af[mt], bf[ng][1], bf[ng][3]);
                    }
            }
        }
        __syncthreads();   // all warps' chunks now staged+waited -> cross-warp visible

        // acc1: hi @ Whi. A k' in [512 + wid*128, +128) (chunks 2/3), B resident
#pragma unroll
        for (int ks = 0; ks < 8; ++ks) {
            const int colA = 512 + wid * 128 + ks * 16 + lcol8;
            const int colB = wid * 128 + ks * 16 + lcol8;
            uint32_t af[2][4];
#pragma unroll
            for (int mt = 0; mt < 2; ++mt)
                ldsm_x4(af[mt][0], af[mt][1], af[mt][2], af[mt][3],
                        sAu + (uint32_t)(mt * 16 + lrow) * ROWB + colA * 2);
            uint32_t bf[3][4];
#pragma unroll
            for (int ng = 0; ng < 3; ++ng)
                ldsm_x4(bf[ng][0], bf[ng][1], bf[ng][2], bf[ng][3],
                        sWu + (uint32_t)(ng * 16 + lrow) * ROWB + colB * 2);
#pragma unroll
            for (int mt = 0; mt < 2; ++mt)
#pragma unroll
                for (int ng = 0; ng < 3; ++ng) {
                    mma_bf16(acc1[mt][ng * 2 + 0], af[mt], bf[ng][0], bf[ng][2]);
                    mma_bf16(acc1[mt][ng * 2 + 1], af[mt], bf[ng][1], bf[ng][3]);
                }
        }

        // combine + write per-warp partials to sRed[w][b][c]
        {
            const int bfr = lane >> 2;
            const int cfr = (lane & 3) * 2;
            float* rw = sRed + wid * (32 * 52);
#pragma unroll
            for (int mt = 0; mt < 2; ++mt)
#pragma unroll
                for (int nt = 0; nt < 6; ++nt) {
                    const int b0 = mt * 16 + bfr;
                    const int c0 = nt * 8 + cfr;
                    float2 v0, v1;
                    v0.x = acc1[mt][nt][0] + acc2[mt][nt][0] * 0.00390625f;
                    v0.y = acc1[mt][nt][1] + acc2[mt][nt][1] * 0.00390625f;
                    v1.x = acc1[mt][nt][2] + acc2[mt][nt][2] * 0.00390625f;
                    v1.y = acc1[mt][nt][3] + acc2[mt][nt][3] * 0.00390625f;
                    *(float2*)(rw + b0 * 52 + c0) = v0;
                    *(float2*)(rw + (b0 + 8) * 52 + c0) = v1;
                }
        }

        // old-h for the z-blend (cols 512+jg -> chunks 2/3, visible post-sync)
        float hv[4];
        {
            const __nv_bfloat16* sAb = (const __nv_bfloat16*)sA;
#pragma unroll
            for (int ii = 0; ii < 4; ++ii) {
                const int jg = jbase + jq * 4 + ii;
                float hi = __bfloat162float(sAb[eb * 1032 + 512 + jg]);
                float lo = __bfloat162float(sAb[eb * 1032 + jg]);
                hv[ii] = hi + lo * 0.00390625f;
            }
        }
        __syncthreads();

        // epilogue: thread handles (b = bbase+eb, j = jbase + jq*4 + ii)
        const float* gib = sGI + (t & 1) * 1536;
        const float rs = g_RS[(t + 1) * BB + bbase + eb];
        float nhv[4];
#pragma unroll
        for (int ii = 0; ii < 4; ++ii) {
            const int cb = (jq * 4 + ii) * 3;
            float aR = 0.f, aZ = 0.f, aN = 0.f;
#pragma unroll
            for (int w = 0; w < 4; ++w) {
                const float* p = sRed + w * (32 * 52) + eb * 52 + cb;
                aR += p[0]; aZ += p[1]; aN += p[2];
            }
            const int jl = jq * 4 + ii;
            const float gir = gib[(0 * 32 + eb) * 16 + jl];
            const float giz = gib[(1 * 32 + eb) * 16 + jl];
            const float gin = gib[(2 * 32 + eb) * 16 + jl];
            const float rr = fsigmoid(aR + gir);
            const float zz = fsigmoid(aZ + giz);
            const float nn = ftanh_fast(gin + rr * (aN + bhn_j[ii]));
            nhv[ii] = (1.f - zz) * nn + zz * hv[ii];
        }
        float4 nh4;
        nh4.x = nhv[0]; nh4.y = nhv[1]; nh4.z = nhv[2]; nh4.w = nhv[3];
        *(float4*)(out + ((size_t)t * BB + bbase + eb) * HH + jbase + jq * 4) = nh4;

        // store next h (reset folded) as bf16 hi/lo, row-major [b][k']
        {
            union { __nv_bfloat16 b[4]; unsigned long long u; } phi, plo;
#pragma unroll
            for (int ii = 0; ii < 4; ++ii) {
                float hn = nhv[ii] * rs;
                __nv_bfloat16 hi = __float2bfloat16(hn);
                __nv_bfloat16 lo = __float2bfloat16((hn - __bfloat162float(hi)) * 256.0f);
                phi.b[ii] = hi; plo.b[ii] = lo;
            }
            const size_t rowb = (size_t)(bbase + eb) * 1024 + jbase + jq * 4;
            *(unsigned long long*)(hdst + rowb) = plo.u;
            *(unsigned long long*)(hdst + rowb + 512) = phi.u;
        }

        // prefetch gi for step t+1
        {
            const int tn = (t + 1 < TT) ? (t + 1) : (TT - 1);
            float* gin_dst = sGI + ((t + 1) & 1) * 1536;
            const float* gin_src = g_GI + (size_t)tn * BB * H3;
#pragma unroll
            for (int q = 0; q < 3; ++q) {
                int p = tid + q * SCAN_THREADS;
                int g = p >> 7, rem = p & 127;
                int b = rem >> 2, j4 = rem & 3;
                cp16(gin_dst + (g * 32 + b) * 16 + j4 * 4,
                     gin_src + (size_t)(bbase + b) * H3 + g * HH + jbase + j4 * 4);
            }
            asm volatile("cp.async.commit_group;");
        }

        // flag-based group barrier: release-store own flag, warp 0 polls all 32
        __syncthreads();
        if (tid == 0) {
            asm volatile("st.release.gpu.global.u32 [%0], %1;"
                         :: "l"(&g_flag[bi][ji]), "r"((unsigned)(t + 1)) : "memory");
        }
        if (tid < 32) {
            unsigned v;
            do {
                asm volatile("ld.relaxed.gpu.global.u32 %0, [%1];"
                             : "=r"(v) : "l"(&g_flag[bi][tid]) : "memory");
            } while (v < (unsigned)(t + 1));
            asm volatile("fence.acq_rel.gpu;" ::: "memory");
        }
        __syncthreads();
    }
}

// ---------------- launch ----------------
extern "C" void kernel_launch(void* const* d_in, const int* in_sizes, int n_in,
                              void* d_out, int out_size) {
    const float* x    = (const float*)d_in[0];   // [T,B,H]
    const void*  rst  = d_in[1];                 // [T,B] bool (unknown storage)
    const float* Wi   = (const float*)d_in[2];   // [H,3H]
    const float* bi   = (const float*)d_in[3];   // [3H]
    const float* Wh   = (const float*)d_in[4];   // [H,3H]
    const float* bhn  = (const float*)d_in[5];   // [H]
    const float* h0   = (const float*)d_in[6];   // [B,H]
    float* out = (float*)d_out;

    (void)in_sizes; (void)n_in; (void)out_size;

    detect_reset_mode_kernel<<<1, 256>>>((const unsigned char*)rst);
    expand_resets_kernel<<<((TT + 1) * BB + 255) / 256, 256>>>(rst);
    init_kernel<<<(BB * HH + 255) / 256, 256>>>(h0);

    // bf16 operand builds
    convert_x_kernel<<<4096, 256>>>(x);
    convert_w_kernel<<<1024, 256>>>(Wi);
    convert_wh_kernel<<<1024, 256>>>(Wh);

    // GI = x @ Wi + bi via HMMA bf16
    cudaFuncSetAttribute(gi_hmma_kernel,
                         cudaFuncAttributeMaxDynamicSharedMemorySize, HB_SMEM_BYTES);
    gi_hmma_kernel<<<6144, 256, HB_SMEM_BYTES>>>(bi);

    // persistent sequential scan (h@Wh on tensor pipe, pipelined staging)
    cudaFuncSetAttribute(scan_kernel,
                         cudaFuncAttributeMaxDynamicSharedMemorySize, SCAN_SMEM_BYTES);
    scan_kernel<<<NCTA, SCAN_THREADS, SCAN_SMEM_BYTES>>>(bhn, out);
}

// round 16
// speedup vs baseline: 2.1229x; 2.1229x over previous
#include <cuda_runtime.h>
#include <cuda_fp16.h>
#include <math.h>
#include <cstdint>

// Problem sizes (fixed by the reference)
#define TT 512
#define BB 128
#define HH 512
#define H3 1536
#define KP2 1024   // fp16 split-K' = 2*HH

// ---------------- scratch (static __device__, no allocs) ----------------
__device__ float g_GI[TT * BB * H3];                // x@Wi + bi (fp32)
__device__ __half g_A2[(size_t)TT * BB * KP2];      // A' = [x_hi | x_lo]
__device__ __half g_WT[(size_t)H3 * KP2];           // W''^T[c] = [Whi(k) | Whi(k)]
__device__ __half g_Hf[2 * BB * 1024];              // h state: [buf][b][hi 0..511 | lo_s 512..1023]
__device__ __half g_Whf[(size_t)H3 * 512];          // Wh rows: [gc][Whi(k)]
__device__ float g_RS[(TT + 1) * BB];               // keep multipliers (0 = reset)
__device__ int   g_reset_mode;
__device__ unsigned int g_cnt[4];                   // per-group barrier counters
__device__ unsigned int g_gen2[4];                  // per-group barrier generations

// ---------------- small PTX helpers ----------------
__device__ __forceinline__ void cp16(void* dst, const void* src) {
    unsigned s = (unsigned)__cvta_generic_to_shared(dst);
    asm volatile("cp.async.cg.shared.global [%0], [%1], 16;" :: "r"(s), "l"(src));
}
__device__ __forceinline__ uint32_t smem_u32(const void* p) {
    return (uint32_t)__cvta_generic_to_shared(p);
}
__device__ __forceinline__ void ldsm_x4(uint32_t& r0, uint32_t& r1,
                                        uint32_t& r2, uint32_t& r3, uint32_t addr) {
    asm volatile("ldmatrix.sync.aligned.m8n8.x4.shared.b16 {%0,%1,%2,%3}, [%4];"
                 : "=r"(r0), "=r"(r1), "=r"(r2), "=r"(r3) : "r"(addr));
}
__device__ __forceinline__ void mma_f16(float* d, const uint32_t* a,
                                        uint32_t b0, uint32_t b1) {
    asm volatile("mma.sync.aligned.m16n8k16.row.col.f32.f16.f16.f32 "
                 "{%0,%1,%2,%3}, {%4,%5,%6,%7}, {%8,%9}, {%0,%1,%2,%3};"
                 : "+f"(d[0]), "+f"(d[1]), "+f"(d[2]), "+f"(d[3])
                 : "r"(a[0]), "r"(a[1]), "r"(a[2]), "r"(a[3]), "r"(b0), "r"(b1));
}
// fast activations: ex2.approx/rcp.approx (rel err ~2^-22), clamped
__device__ __forceinline__ float fsigmoid(float x) {
    x = fminf(30.f, fmaxf(-30.f, x));
    float e;
    asm("ex2.approx.f32 %0, %1;" : "=f"(e) : "f"(-1.4426950408889634f * x));
    float r;
    asm("rcp.approx.f32 %0, %1;" : "=f"(r) : "f"(1.0f + e));
    return r;
}
__device__ __forceinline__ float ftanh_fast(float x) {
    x = fminf(30.f, fmaxf(-30.f, x));
    float e;
    asm("ex2.approx.f32 %0, %1;" : "=f"(e) : "f"(-2.8853900817779268f * x));
    float r;
    asm("rcp.approx.f32 %0, %1;" : "=f"(r) : "f"(1.0f + e));
    return (1.0f - e) * r;
}

// ---------------- detect how the harness stored the bool resets ----------
__global__ void detect_reset_mode_kernel(const unsigned char* __restrict__ r) {
    __shared__ int cnt[4];
    if (threadIdx.x < 4) cnt[threadIdx.x] = 0;
    __syncthreads();
    int local[4] = {0, 0, 0, 0};
    const uchar4* r4 = (const uchar4*)r;
    for (int i = threadIdx.x; i < (TT * BB) / 4; i += blockDim.x) {
        uchar4 v = r4[i];
        local[0] += (v.x != 0); local[1] += (v.y != 0);
        local[2] += (v.z != 0); local[3] += (v.w != 0);
    }
#pragma unroll
    for (int q = 0; q < 4; ++q) atomicAdd(&cnt[q], local[q]);
    __syncthreads();
    if (threadIdx.x == 0) {
        int mode;
        if (cnt[1] > 0) mode = 1;
        else if (cnt[0] > 0) mode = 0;
        else if (cnt[2] > 0 || cnt[3] > 0) mode = 2;
        else mode = 0;
        g_reset_mode = mode;
    }
}

__global__ void expand_resets_kernel(const void* __restrict__ resets) {
    int i = blockIdx.x * blockDim.x + threadIdx.x;
    if (i >= (TT + 1) * BB) return;
    if (i >= TT * BB) { g_RS[i] = 1.0f; return; }
    const int mode = g_reset_mode;
    bool rst;
    if (mode == 0)      rst = ((const int*)resets)[i] != 0;
    else if (mode == 1) rst = ((const unsigned char*)resets)[i] != 0;
    else                rst = ((const float*)resets)[i] != 0.0f;
    g_RS[i] = rst ? 0.0f : 1.0f;
}

// init: barrier state + h0 (reset-applied, fp16 hi/lo_s split, [b][hi|lo])
__global__ void init_kernel(const float* __restrict__ h0) {
    int i = blockIdx.x * blockDim.x + threadIdx.x;
    if (i < 4) { g_cnt[i] = 0u; g_gen2[i] = 0u; }
    if (i < BB * HH) {
        int b = i >> 9;
        int j = i & (HH - 1);
        float h = h0[i] * g_RS[b];
        __half hi = __float2half(h);
        __half lo = __float2half((h - __half2float(hi)) * 2048.0f);
        g_Hf[b * 1024 + j] = hi;
        g_Hf[b * 1024 + 512 + j] = lo;
    }
}

// ---------------- split-fp32 -> fp16 conversion kernels ----------------
__global__ void convert_x_kernel(const float* __restrict__ x) {
    const int n = TT * BB * HH;
    for (int idx = blockIdx.x * blockDim.x + threadIdx.x; idx < n;
         idx += gridDim.x * blockDim.x) {
        int m = idx >> 9, k = idx & 511;
        float v = x[idx];
        __half hi = __float2half(v);
        __half lo = __float2half(v - __half2float(hi));
        size_t base = (size_t)m * KP2;
        g_A2[base + k] = hi;
        g_A2[base + 512 + k] = lo;
    }
}
__global__ void convert_w_kernel(const float* __restrict__ Wi) {
    const int n = HH * H3;
    for (int idx = blockIdx.x * blockDim.x + threadIdx.x; idx < n;
         idx += gridDim.x * blockDim.x) {
        int k = idx / H3, c = idx % H3;          // Wi[k][c]
        __half hi = __float2half(Wi[idx]);
        size_t base = (size_t)c * KP2;
        g_WT[base + k] = hi;
        g_WT[base + 512 + k] = hi;
    }
}
// Wh -> g_Whf rows: [gc][Whi(k)]
__global__ void convert_wh_kernel(const float* __restrict__ Wh) {
    const int n = HH * H3;
    for (int idx = blockIdx.x * blockDim.x + threadIdx.x; idx < n;
         idx += gridDim.x * blockDim.x) {
        int gc = idx >> 9, k = idx & 511;
        g_Whf[(size_t)gc * 512 + k] = __float2half(Wh[(size_t)k * H3 + gc]);
    }
}

// ---------------- GI GEMM via mma.sync fp16 (HMMA), K'=1024 --------------
#define HBM_M 128
#define HBM_N 128
#define HBM_K 32
#define APITCH 40
#define STAGE_BYTES 20480
#define NSTAGE 3
#define HB_BIAS_OFF (NSTAGE * STAGE_BYTES)
#define HB_SMEM_BYTES (HB_BIAS_OFF + 512)
#define NC (KP2 / HBM_K)     // 32 chunks

extern __shared__ float smf[];

__device__ __forceinline__ void hmma_stage(char* smc, int slot, int kc,
                                           const __half* Ag,
                                           const __half* Bg, int tid) {
    char* sA = smc + slot * STAGE_BYTES;
    char* sB = sA + 10240;
    const int k0 = kc * HBM_K;
#pragma unroll
    for (int i = 0; i < 2; ++i) {
        int id = tid * 2 + i;
        int row = id >> 2, seg = id & 3;
        cp16(sA + row * 80 + seg * 16, Ag + (size_t)row * KP2 + k0 + seg * 8);
        cp16(sB + row * 80 + seg * 16, Bg + (size_t)row * KP2 + k0 + seg * 8);
    }
}

__global__ __launch_bounds__(256) void gi_hmma_kernel(const float* __restrict__ bias) {
    char* smc = (char*)smf;
    const uint32_t sbase = smem_u32(smc);
    const int tid = threadIdx.x;
    const int lane = tid & 31, warp = tid >> 5;
    const int wm = warp >> 1, wn = warp & 1;

    const int bid = blockIdx.x;
    const int grp = bid / 96, r = bid % 96;
    const int ntile = r % 12, mtile = grp * 8 + r / 12;
    const int m0 = mtile * HBM_M, n0 = ntile * HBM_N;
    const __half* Ag = g_A2 + (size_t)m0 * KP2;
    const __half* Bg = g_WT + (size_t)n0 * KP2;

    float* bsm = (float*)(smc + HB_BIAS_OFF);
    if (tid < 128) bsm[tid] = bias[n0 + tid];

    float acc[2][8][4];
#pragma unroll
    for (int mt = 0; mt < 2; ++mt)
#pragma unroll
        for (int nt = 0; nt < 8; ++nt)
#pragma unroll
            for (int q = 0; q < 4; ++q) acc[mt][nt][q] = 0.f;

    hmma_stage(smc, 0, 0, Ag, Bg, tid);
    asm volatile("cp.async.commit_group;");
    hmma_stage(smc, 1, 1, Ag, Bg, tid);
    asm volatile("cp.async.commit_group;");

    const int lrow = lane & 15;
    const int lcol8 = (lane >> 4) * 8;

    for (int c = 0; c < NC; ++c) {
        if (c == NC - 1) asm volatile("cp.async.wait_group 0;");
        else             asm volatile("cp.async.wait_group 1;");
        __syncthreads();
        if (c + 2 < NC) {
            hmma_stage(smc, (c + 2) % NSTAGE, c + 2, Ag, Bg, tid);
            asm volatile("cp.async.commit_group;");
        }

        const uint32_t aBase = sbase + (uint32_t)(c % NSTAGE) * STAGE_BYTES;
        const uint32_t bBase = aBase + 10240;

#pragma unroll
        for (int ks = 0; ks < 2; ++ks) {
            const int col = ks * 16 + lcol8;
            uint32_t af[2][4];
#pragma unroll
            for (int mt = 0; mt < 2; ++mt) {
                uint32_t addr = aBase +
                    (uint32_t)((wm * 32 + mt * 16 + lrow) * APITCH + col) * 2;
                ldsm_x4(af[mt][0], af[mt][1], af[mt][2], af[mt][3], addr);
            }
            uint32_t bf[4][4];
#pragma unroll
            for (int ng = 0; ng < 4; ++ng) {
                uint32_t addr = bBase +
                    (uint32_t)((wn * 64 + ng * 16 + lrow) * APITCH + col) * 2;
                ldsm_x4(bf[ng][0], bf[ng][1], bf[ng][2], bf[ng][3], addr);
            }
#pragma unroll
            for (int mt = 0; mt < 2; ++mt)
#pragma unroll
                for (int ng = 0; ng < 4; ++ng) {
                    mma_f16(acc[mt][ng * 2 + 0], af[mt], bf[ng][0], bf[ng][2]);
                    mma_f16(acc[mt][ng * 2 + 1], af[mt], bf[ng][1], bf[ng][3]);
                }
        }
        __syncthreads();
    }

    const int ml = lane >> 2;
    const int nl = (lane & 3) * 2;
#pragma unroll
    for (int mt = 0; mt < 2; ++mt) {
        const int mg = m0 + wm * 32 + mt * 16 + ml;
#pragma unroll
        for (int nt = 0; nt < 8; ++nt) {
            const int ncol = wn * 64 + nt * 8 + nl;
            const float b0 = bsm[ncol], b1 = bsm[ncol + 1];
            float2 v0, v1;
            v0.x = acc[mt][nt][0] + b0; v0.y = acc[mt][nt][1] + b1;
            v1.x = acc[mt][nt][2] + b0; v1.y = acc[mt][nt][3] + b1;
            *(float2*)(g_GI + (size_t)mg * H3 + n0 + ncol) = v0;
            *(float2*)(g_GI + (size_t)(mg + 8) * H3 + n0 + ncol) = v1;
        }
    }
}

// ---------------- persistent scan kernel: h@Wh via fp16 HMMA -------------
#define NCTA 128
#define SCAN_THREADS 128
#define ROWB 2064     // bytes per h smem row (2048 data + 16 pad)
#define WROWB 1040    // bytes per weight smem row (1024 data + 16 pad)
#define SW_OFF   0
#define SA_OFF   49920                       // 48*1040
#define SGI_OFF  (49920 + 66048)             // = 115968
#define SRED_OFF (115968 + 12288)            // = 128256
#define SCAN_SMEM_BYTES (128256 + 26624)     // = 154880

__device__ __forceinline__ void group_sync(int bi, unsigned int& gen) {
    __syncthreads();
    if (threadIdx.x == 0) {
        unsigned int prev;
        asm volatile("atom.acq_rel.gpu.add.u32 %0, [%1], 1;"
                     : "=r"(prev) : "l"(&g_cnt[bi]) : "memory");
        if (prev == 31u) {
            asm volatile("st.relaxed.gpu.u32 [%0], 0;" :: "l"(&g_cnt[bi]) : "memory");
            unsigned int d;
            asm volatile("atom.release.gpu.add.u32 %0, [%1], 1;"
                         : "=r"(d) : "l"(&g_gen2[bi]) : "memory");
        } else {
            unsigned int cur;
            do {
                asm volatile("ld.acquire.gpu.u32 %0, [%1];"
                             : "=r"(cur) : "l"(&g_gen2[bi]) : "memory");
            } while (cur == gen);
        }
    }
    gen++;
    __syncthreads();
}

__global__ __launch_bounds__(SCAN_THREADS, 1) void scan_kernel(
    const float* __restrict__ bhn,             // [H]
    float* __restrict__ out)                   // [T,B,H]
{
    char* smc = (char*)smf;
    char* sW  = smc + SW_OFF;                  // 48 rows x 1040B: [c][Whi]
    char* sA  = smc + SA_OFF;                  // 32 rows x 2064B: [b][hi|lo_s]
    float* sGI  = (float*)(smc + SGI_OFF);     // [2][3][32][16]
    float* sRed = (float*)(smc + SRED_OFF);    // [4][32][52]
    const uint32_t sWu = smem_u32(sW);
    const uint32_t sAu = smem_u32(sA);

    const int tid  = threadIdx.x;
    const int lane = tid & 31;
    const int wid  = tid >> 5;
    const int ji   = blockIdx.x & 31;
    const int bi   = blockIdx.x >> 5;
    const int jbase = ji * 16;
    const int bbase = bi * 32;
    const int eb = tid & 31;
    const int jq = tid >> 5;

    // stage weights once: 48 rows of 1024B
    for (int p = tid; p < 48 * 64; p += SCAN_THREADS) {
        int row = p >> 6, seg = p & 63;
        int gc = (row % 3) * HH + jbase + row / 3;   // c = jl*3+g -> gc
        cp16(sW + row * WROWB + seg * 16, g_Whf + (size_t)gc * 512 + seg * 8);
    }
    // prefetch gi for t=0 into buffer 0
#pragma unroll
    for (int q = 0; q < 3; ++q) {
        int p = tid + q * SCAN_THREADS;
        int g = p >> 7, rem = p & 127;
        int b = rem >> 2, j4 = rem & 3;
        cp16(sGI + (g * 32 + b) * 16 + j4 * 4,
             g_GI + (size_t)(bbase + b) * H3 + g * HH + jbase + j4 * 4);
    }
    asm volatile("cp.async.commit_group;");

    float bhn_j[4];
#pragma unroll
    for (int ii = 0; ii < 4; ++ii) bhn_j[ii] = bhn[jbase + jq * 4 + ii];

    const int lrow = lane & 15;
    const int lcol8 = (lane >> 4) * 8;
    const float myScale = (wid < 2) ? 1.0f : 4.8828125e-4f;   // lo warps: 2^-11
    unsigned int gen = 0;

    for (int t = 0; t < TT; ++t) {
        const __half* hsrc = g_Hf + (t & 1) * BB * 1024;
        __half* hdst       = g_Hf + ((t + 1) & 1) * BB * 1024;

        // stage h slice: 32 rows x 2048B
#pragma unroll
        for (int q = 0; q < 32; ++q) {
            int p = tid + q * SCAN_THREADS;
            int row = p >> 7, seg = p & 127;
            cp16(sA + row * ROWB + seg * 16,
                 hsrc + (size_t)(bbase + row) * 1024 + seg * 8);
        }
        asm volatile("cp.async.commit_group;");
        asm volatile("cp.async.wait_group 0;");
        __syncthreads();

        // single fp16 pass, 4-way k'-split: warps 0,1 -> hi@Whi (scale 1),
        // warps 2,3 -> lo_s@Whi (scale 2^-11)
        float acc[2][6][4];
#pragma unroll
        for (int mt = 0; mt < 2; ++mt)
#pragma unroll
            for (int nt = 0; nt < 6; ++nt)
#pragma unroll
                for (int q = 0; q < 4; ++q) acc[mt][nt][q] = 0.f;

#pragma unroll
        for (int ks = 0; ks < 16; ++ks) {
            const int colA = wid * 256 + ks * 16 + lcol8;
            const int colB = ((wid & 1) ? 256 : 0) + ks * 16 + lcol8;
            uint32_t af[2][4];
#pragma unroll
            for (int mt = 0; mt < 2; ++mt)
                ldsm_x4(af[mt][0], af[mt][1], af[mt][2], af[mt][3],
                        sAu + (uint32_t)(mt * 16 + lrow) * ROWB + colA * 2);
            uint32_t bf[3][4];
#pragma unroll
            for (int ng = 0; ng < 3; ++ng)
                ldsm_x4(bf[ng][0], bf[ng][1], bf[ng][2], bf[ng][3],
                        sWu + (uint32_t)(ng * 16 + lrow) * WROWB + colB * 2);
#pragma unroll
            for (int mt = 0; mt < 2; ++mt)
#pragma unroll
                for (int ng = 0; ng < 3; ++ng) {
                    mma_f16(acc[mt][ng * 2 + 0], af[mt], bf[ng][0], bf[ng][2]);
                    mma_f16(acc[mt][ng * 2 + 1], af[mt], bf[ng][1], bf[ng][3]);
                }
        }

        // write per-warp partials to sRed[w][b][c] (lo warps pre-scaled)
        {
            const int bfr = lane >> 2;
            const int cfr = (lane & 3) * 2;
            float* rw = sRed + wid * (32 * 52);
#pragma unroll
            for (int mt = 0; mt < 2; ++mt)
#pragma unroll
                for (int nt = 0; nt < 6; ++nt) {
                    const int b0 = mt * 16 + bfr;
                    const int c0 = nt * 8 + cfr;
                    float2 v0, v1;
                    v0.x = acc[mt][nt][0] * myScale; v0.y = acc[mt][nt][1] * myScale;
                    v1.x = acc[mt][nt][2] * myScale; v1.y = acc[mt][nt][3] * myScale;
                    *(float2*)(rw + b0 * 52 + c0) = v0;
                    *(float2*)(rw + (b0 + 8) * 52 + c0) = v1;
                }
        }

        // old-h for the z-blend, reconstructed exactly from staged hi/lo
        float hv[4];
        {
            const __half* sAb = (const __half*)sA;
#pragma unroll
            for (int ii = 0; ii < 4; ++ii) {
                const int jg = jbase + jq * 4 + ii;
                float hi = __half2float(sAb[eb * 1032 + jg]);
                float lo = __half2float(sAb[eb * 1032 + 512 + jg]);
                hv[ii] = hi + lo * 4.8828125e-4f;
            }
        }
        __syncthreads();

        // epilogue: thread handles (b = bbase+eb, j = jbase + jq*4 + ii)
        const float* gib = sGI + (t & 1) * 1536;
        const float rs = g_RS[(t + 1) * BB + bbase + eb];
        float nhv[4];
#pragma unroll
        for (int ii = 0; ii < 4; ++ii) {
            const int cb = (jq * 4 + ii) * 3;
            float aR = 0.f, aZ = 0.f, aN = 0.f;
#pragma unroll
            for (int w = 0; w < 4; ++w) {
                const float* p = sRed + w * (32 * 52) + eb * 52 + cb;
                aR += p[0]; aZ += p[1]; aN += p[2];
            }
            const int jl = jq * 4 + ii;
            const float gir = gib[(0 * 32 + eb) * 16 + jl];
            const float giz = gib[(1 * 32 + eb) * 16 + jl];
            const float gin = gib[(2 * 32 + eb) * 16 + jl];
            const float rr = fsigmoid(aR + gir);
            const float zz = fsigmoid(aZ + giz);
            const float nn = ftanh_fast(gin + rr * (aN + bhn_j[ii]));
            nhv[ii] = (1.f - zz) * nn + zz * hv[ii];
        }
        float4 nh4;
        nh4.x = nhv[0]; nh4.y = nhv[1]; nh4.z = nhv[2]; nh4.w = nhv[3];
        *(float4*)(out + ((size_t)t * BB + bbase + eb) * HH + jbase + jq * 4) = nh4;

        // store next h (reset folded) as fp16 hi/lo_s, row-major [b][hi|lo]
        {
            union { __half b[4]; unsigned long long u; } phi, plo;
#pragma unroll
            for (int ii = 0; ii < 4; ++ii) {
                float hn = nhv[ii] * rs;
                __half hi = __float2half(hn);
                __half lo = __float2half((hn - __half2float(hi)) * 2048.0f);
                phi.b[ii] = hi; plo.b[ii] = lo;
            }
            const size_t rowb = (size_t)(bbase + eb) * 1024 + jbase + jq * 4;
            *(unsigned long long*)(hdst + rowb) = phi.u;
            *(unsigned long long*)(hdst + rowb + 512) = plo.u;
        }

        // prefetch gi for step t+1
        {
            const int tn = (t + 1 < TT) ? (t + 1) : (TT - 1);
            float* gin_dst = sGI + ((t + 1) & 1) * 1536;
            const float* gin_src = g_GI + (size_t)tn * BB * H3;
#pragma unroll
            for (int q = 0; q < 3; ++q) {
                int p = tid + q * SCAN_THREADS;
                int g = p >> 7, rem = p & 127;
                int b = rem >> 2, j4 = rem & 3;
                cp16(gin_dst + (g * 32 + b) * 16 + j4 * 4,
                     gin_src + (size_t)(bbase + b) * H3 + g * HH + jbase + j4 * 4);
            }
            asm volatile("cp.async.commit_group;");
        }

        group_sync(bi, gen);
    }
}

// ---------------- launch ----------------
extern "C" void kernel_launch(void* const* d_in, const int* in_sizes, int n_in,
                              void* d_out, int out_size) {
    const float* x    = (const float*)d_in[0];   // [T,B,H]
    const void*  rst  = d_in[1];                 // [T,B] bool (unknown storage)
    const float* Wi   = (const float*)d_in[2];   // [H,3H]
    const float* bi   = (const float*)d_in[3];   // [3H]
    const float* Wh   = (const float*)d_in[4];   // [H,3H]
    const float* bhn  = (const float*)d_in[5];   // [H]
    const float* h0   = (const float*)d_in[6];   // [B,H]
    float* out = (float*)d_out;

    (void)in_sizes; (void)n_in; (void)out_size;

    detect_reset_mode_kernel<<<1, 256>>>((const unsigned char*)rst);
    expand_resets_kernel<<<((TT + 1) * BB + 255) / 256, 256>>>(rst);
    init_kernel<<<(BB * HH + 255) / 256, 256>>>(h0);

    // fp16 operand builds
    convert_x_kernel<<<4096, 256>>>(x);
    convert_w_kernel<<<1024, 256>>>(Wi);
    convert_wh_kernel<<<1024, 256>>>(Wh);

    // GI = x @ Wi + bi via HMMA fp16 (split-K' = 1024)
    cudaFuncSetAttribute(gi_hmma_kernel,
                         cudaFuncAttributeMaxDynamicSharedMemorySize, HB_SMEM_BYTES);
    gi_hmma_kernel<<<6144, 256, HB_SMEM_BYTES>>>(bi);

    // persistent sequential scan (h@Wh on tensor pipe, fp16 2-term split)
    cudaFuncSetAttribute(scan_kernel,
                         cudaFuncAttributeMaxDynamicSharedMemorySize, SCAN_SMEM_BYTES);
    scan_kernel<<<NCTA, SCAN_THREADS, SCAN_SMEM_BYTES>>>(bhn, out);
}

// round 17
// speedup vs baseline: 2.1872x; 1.0303x over previous
#include <cuda_runtime.h>
#include <cuda_fp16.h>
#include <math.h>
#include <cstdint>

// Problem sizes (fixed by the reference)
#define TT 512
#define BB 128
#define HH 512
#define H3 1536
#define KP2 1024   // fp16 split-K' = 2*HH

// ---------------- scratch (static __device__, no allocs) ----------------
__device__ __half g_GI[(size_t)TT * BB * H3];       // x@Wi + bi (fp16)
__device__ __half g_A2[(size_t)TT * BB * KP2];      // A' = [x_hi | x_lo]
__device__ __half g_WT[(size_t)H3 * KP2];           // W''^T[c] = [Whi(k) | Whi(k)]
__device__ __half g_Hf[2 * BB * 1024];              // h state: [buf][b][hi 0..511 | lo_s 512..1023]
__device__ __half g_Whf[(size_t)H3 * 512];          // Wh rows: [gc][Whi(k)]
__device__ float g_RS[(TT + 1) * BB];               // keep multipliers (0 = reset)
__device__ int   g_reset_mode;
__device__ unsigned int g_cnt[4];                   // per-group barrier counters
__device__ unsigned int g_gen2[4];                  // per-group barrier generations

// ---------------- small PTX helpers ----------------
__device__ __forceinline__ void cp16(void* dst, const void* src) {
    unsigned s = (unsigned)__cvta_generic_to_shared(dst);
    asm volatile("cp.async.cg.shared.global [%0], [%1], 16;" :: "r"(s), "l"(src));
}
__device__ __forceinline__ uint32_t smem_u32(const void* p) {
    return (uint32_t)__cvta_generic_to_shared(p);
}
__device__ __forceinline__ void ldsm_x4(uint32_t& r0, uint32_t& r1,
                                        uint32_t& r2, uint32_t& r3, uint32_t addr) {
    asm volatile("ldmatrix.sync.aligned.m8n8.x4.shared.b16 {%0,%1,%2,%3}, [%4];"
                 : "=r"(r0), "=r"(r1), "=r"(r2), "=r"(r3) : "r"(addr));
}
__device__ __forceinline__ void mma_f16(float* d, const uint32_t* a,
                                        uint32_t b0, uint32_t b1) {
    asm volatile("mma.sync.aligned.m16n8k16.row.col.f32.f16.f16.f32 "
                 "{%0,%1,%2,%3}, {%4,%5,%6,%7}, {%8,%9}, {%0,%1,%2,%3};"
                 : "+f"(d[0]), "+f"(d[1]), "+f"(d[2]), "+f"(d[3])
                 : "r"(a[0]), "r"(a[1]), "r"(a[2]), "r"(a[3]), "r"(b0), "r"(b1));
}
// fast activations: ex2.approx/rcp.approx (rel err ~2^-22), clamped
__device__ __forceinline__ float fsigmoid(float x) {
    x = fminf(30.f, fmaxf(-30.f, x));
    float e;
    asm("ex2.approx.f32 %0, %1;" : "=f"(e) : "f"(-1.4426950408889634f * x));
    float r;
    asm("rcp.approx.f32 %0, %1;" : "=f"(r) : "f"(1.0f + e));
    return r;
}
__device__ __forceinline__ float ftanh_fast(float x) {
    x = fminf(30.f, fmaxf(-30.f, x));
    float e;
    asm("ex2.approx.f32 %0, %1;" : "=f"(e) : "f"(-2.8853900817779268f * x));
    float r;
    asm("rcp.approx.f32 %0, %1;" : "=f"(r) : "f"(1.0f + e));
    return (1.0f - e) * r;
}

// ---------------- detect how the harness stored the bool resets ----------
__global__ void detect_reset_mode_kernel(const unsigned char* __restrict__ r) {
    __shared__ int cnt[4];
    if (threadIdx.x < 4) cnt[threadIdx.x] = 0;
    __syncthreads();
    int local[4] = {0, 0, 0, 0};
    const uchar4* r4 = (const uchar4*)r;
    for (int i = threadIdx.x; i < (TT * BB) / 4; i += blockDim.x) {
        uchar4 v = r4[i];
        local[0] += (v.x != 0); local[1] += (v.y != 0);
        local[2] += (v.z != 0); local[3] += (v.w != 0);
    }
#pragma unroll
    for (int q = 0; q < 4; ++q) atomicAdd(&cnt[q], local[q]);
    __syncthreads();
    if (threadIdx.x == 0) {
        int mode;
        if (cnt[1] > 0) mode = 1;
        else if (cnt[0] > 0) mode = 0;
        else if (cnt[2] > 0 || cnt[3] > 0) mode = 2;
        else mode = 0;
        g_reset_mode = mode;
    }
}

__global__ void expand_resets_kernel(const void* __restrict__ resets) {
    int i = blockIdx.x * blockDim.x + threadIdx.x;
    if (i >= (TT + 1) * BB) return;
    if (i >= TT * BB) { g_RS[i] = 1.0f; return; }
    const int mode = g_reset_mode;
    bool rst;
    if (mode == 0)      rst = ((const int*)resets)[i] != 0;
    else if (mode == 1) rst = ((const unsigned char*)resets)[i] != 0;
    else                rst = ((const float*)resets)[i] != 0.0f;
    g_RS[i] = rst ? 0.0f : 1.0f;
}

// init: barrier state + h0 (reset-applied, fp16 hi/lo_s split, [b][hi|lo])
__global__ void init_kernel(const float* __restrict__ h0) {
    int i = blockIdx.x * blockDim.x + threadIdx.x;
    if (i < 4) { g_cnt[i] = 0u; g_gen2[i] = 0u; }
    if (i < BB * HH) {
        int b = i >> 9;
        int j = i & (HH - 1);
        float h = h0[i] * g_RS[b];
        __half hi = __float2half(h);
        __half lo = __float2half((h - __half2float(hi)) * 2048.0f);
        g_Hf[b * 1024 + j] = hi;
        g_Hf[b * 1024 + 512 + j] = lo;
    }
}

// ---------------- split-fp32 -> fp16 conversion kernels ----------------
__global__ void convert_x_kernel(const float* __restrict__ x) {
    const int n4 = TT * BB * HH / 4;
    const float4* x4 = (const float4*)x;
    for (int idx = blockIdx.x * blockDim.x + threadIdx.x; idx < n4;
         idx += gridDim.x * blockDim.x) {
        int m = idx >> 7, k4 = (idx & 127) * 4;
        float4 v = x4[idx];
        __half2 h0 = __floats2half2_rn(v.x, v.y);
        __half2 h1 = __floats2half2_rn(v.z, v.w);
        __half2 l0 = __floats2half2_rn(v.x - __half2float(__low2half(h0)),
                                       v.y - __half2float(__high2half(h0)));
        __half2 l1 = __floats2half2_rn(v.z - __half2float(__low2half(h1)),
                                       v.w - __half2float(__high2half(h1)));
        size_t base = (size_t)m * KP2 + k4;
        union { __half2 h[2]; uint2 u; } phi, plo;
        phi.h[0] = h0; phi.h[1] = h1;
        plo.h[0] = l0; plo.h[1] = l1;
        *(uint2*)(g_A2 + base) = phi.u;
        *(uint2*)(g_A2 + base + 512) = plo.u;
    }
}
__global__ void convert_w_kernel(const float* __restrict__ Wi) {
    const int n = HH * H3;
    for (int idx = blockIdx.x * blockDim.x + threadIdx.x; idx < n;
         idx += gridDim.x * blockDim.x) {
        int k = idx / H3, c = idx % H3;          // Wi[k][c]
        __half hi = __float2half(Wi[idx]);
        size_t base = (size_t)c * KP2;
        g_WT[base + k] = hi;
        g_WT[base + 512 + k] = hi;
    }
}
// Wh -> g_Whf rows: [gc][Whi(k)]
__global__ void convert_wh_kernel(const float* __restrict__ Wh) {
    const int n = HH * H3;
    for (int idx = blockIdx.x * blockDim.x + threadIdx.x; idx < n;
         idx += gridDim.x * blockDim.x) {
        int gc = idx >> 9, k = idx & 511;
        g_Whf[(size_t)gc * 512 + k] = __float2half(Wh[(size_t)k * H3 + gc]);
    }
}

// ---------------- GI GEMM via mma.sync fp16 (HMMA), K'=1024 --------------
#define HBM_M 128
#define HBM_N 128
#define HBM_K 32
#define APITCH 40
#define STAGE_BYTES 20480
#define NSTAGE 3
#define HB_BIAS_OFF (NSTAGE * STAGE_BYTES)
#define HB_SMEM_BYTES (HB_BIAS_OFF + 512)
#define NC (KP2 / HBM_K)     // 32 chunks

extern __shared__ float smf[];

__device__ __forceinline__ void hmma_stage(char* smc, int slot, int kc,
                                           const __half* Ag,
                                           const __half* Bg, int tid) {
    char* sA = smc + slot * STAGE_BYTES;
    char* sB = sA + 10240;
    const int k0 = kc * HBM_K;
#pragma unroll
    for (int i = 0; i < 2; ++i) {
        int id = tid * 2 + i;
        int row = id >> 2, seg = id & 3;
        cp16(sA + row * 80 + seg * 16, Ag + (size_t)row * KP2 + k0 + seg * 8);
        cp16(sB + row * 80 + seg * 16, Bg + (size_t)row * KP2 + k0 + seg * 8);
    }
}

__global__ __launch_bounds__(256) void gi_hmma_kernel(const float* __restrict__ bias) {
    char* smc = (char*)smf;
    const uint32_t sbase = smem_u32(smc);
    const int tid = threadIdx.x;
    const int lane = tid & 31, warp = tid >> 5;
    const int wm = warp >> 1, wn = warp & 1;

    const int bid = blockIdx.x;
    const int grp = bid / 96, r = bid % 96;
    const int ntile = r % 12, mtile = grp * 8 + r / 12;
    const int m0 = mtile * HBM_M, n0 = ntile * HBM_N;
    const __half* Ag = g_A2 + (size_t)m0 * KP2;
    const __half* Bg = g_WT + (size_t)n0 * KP2;

    float* bsm = (float*)(smc + HB_BIAS_OFF);
    if (tid < 128) bsm[tid] = bias[n0 + tid];

    float acc[2][8][4];
#pragma unroll
    for (int mt = 0; mt < 2; ++mt)
#pragma unroll
        for (int nt = 0; nt < 8; ++nt)
#pragma unroll
            for (int q = 0; q < 4; ++q) acc[mt][nt][q] = 0.f;

    hmma_stage(smc, 0, 0, Ag, Bg, tid);
    asm volatile("cp.async.commit_group;");
    hmma_stage(smc, 1, 1, Ag, Bg, tid);
    asm volatile("cp.async.commit_group;");

    const int lrow = lane & 15;
    const int lcol8 = (lane >> 4) * 8;

    for (int c = 0; c < NC; ++c) {
        if (c == NC - 1) asm volatile("cp.async.wait_group 0;");
        else             asm volatile("cp.async.wait_group 1;");
        __syncthreads();
        if (c + 2 < NC) {
            hmma_stage(smc, (c + 2) % NSTAGE, c + 2, Ag, Bg, tid);
            asm volatile("cp.async.commit_group;");
        }

        const uint32_t aBase = sbase + (uint32_t)(c % NSTAGE) * STAGE_BYTES;
        const uint32_t bBase = aBase + 10240;

#pragma unroll
        for (int ks = 0; ks < 2; ++ks) {
            const int col = ks * 16 + lcol8;
            uint32_t af[2][4];
#pragma unroll
            for (int mt = 0; mt < 2; ++mt) {
                uint32_t addr = aBase +
                    (uint32_t)((wm * 32 + mt * 16 + lrow) * APITCH + col) * 2;
                ldsm_x4(af[mt][0], af[mt][1], af[mt][2], af[mt][3], addr);
            }
            uint32_t bf[4][4];
#pragma unroll
            for (int ng = 0; ng < 4; ++ng) {
                uint32_t addr = bBase +
                    (uint32_t)((wn * 64 + ng * 16 + lrow) * APITCH + col) * 2;
                ldsm_x4(bf[ng][0], bf[ng][1], bf[ng][2], bf[ng][3], addr);
            }
#pragma unroll
            for (int mt = 0; mt < 2; ++mt)
#pragma unroll
                for (int ng = 0; ng < 4; ++ng) {
                    mma_f16(acc[mt][ng * 2 + 0], af[mt], bf[ng][0], bf[ng][2]);
                    mma_f16(acc[mt][ng * 2 + 1], af[mt], bf[ng][1], bf[ng][3]);
                }
        }
        __syncthreads();
    }

    // epilogue: add bias, store fp16
    const int ml = lane >> 2;
    const int nl = (lane & 3) * 2;
#pragma unroll
    for (int mt = 0; mt < 2; ++mt) {
        const int mg = m0 + wm * 32 + mt * 16 + ml;
#pragma unroll
        for (int nt = 0; nt < 8; ++nt) {
            const int ncol = wn * 64 + nt * 8 + nl;
            const float b0 = bsm[ncol], b1 = bsm[ncol + 1];
            __half2 v0 = __floats2half2_rn(acc[mt][nt][0] + b0, acc[mt][nt][1] + b1);
            __half2 v1 = __floats2half2_rn(acc[mt][nt][2] + b0, acc[mt][nt][3] + b1);
            *(__half2*)(g_GI + (size_t)mg * H3 + n0 + ncol) = v0;
            *(__half2*)(g_GI + (size_t)(mg + 8) * H3 + n0 + ncol) = v1;
        }
    }
}

// ---------------- persistent scan kernel: h@Wh via fp16 HMMA -------------
#define NCTA 128
#define SCAN_THREADS 128
#define ROWB 2064     // bytes per h smem row (2048 data + 16 pad)
#define WROWB 1040    // bytes per weight smem row (1024 data + 16 pad)
#define SW_OFF   0
#define SA_OFF   49920                       // 48*1040
#define SGI_OFF  (49920 + 66048)             // = 115968 (2 x 1536 halves = 6144 B)
#define SRED_OFF (115968 + 6144)             // = 122112
#define SCAN_SMEM_BYTES (122112 + 26624)     // = 148736

__device__ __forceinline__ void group_sync(int bi, unsigned int& gen) {
    __syncthreads();
    if (threadIdx.x == 0) {
        unsigned int prev;
        asm volatile("atom.acq_rel.gpu.add.u32 %0, [%1], 1;"
                     : "=r"(prev) : "l"(&g_cnt[bi]) : "memory");
        if (prev == 31u) {
            asm volatile("st.relaxed.gpu.u32 [%0], 0;" :: "l"(&g_cnt[bi]) : "memory");
            unsigned int d;
            asm volatile("atom.release.gpu.add.u32 %0, [%1], 1;"
                         : "=r"(d) : "l"(&g_gen2[bi]) : "memory");
        } else {
            unsigned int cur;
            do {
                asm volatile("ld.acquire.gpu.u32 %0, [%1];"
                             : "=r"(cur) : "l"(&g_gen2[bi]) : "memory");
            } while (cur == gen);
        }
    }
    gen++;
    __syncthreads();
}

__global__ __launch_bounds__(SCAN_THREADS, 1) void scan_kernel(
    const float* __restrict__ bhn,             // [H]
    float* __restrict__ out)                   // [T,B,H]
{
    char* smc = (char*)smf;
    char* sW  = smc + SW_OFF;                  // 48 rows x 1040B: [c][Whi]
    char* sA  = smc + SA_OFF;                  // 32 rows x 2064B: [b][hi|lo_s]
    __half* sGI = (__half*)(smc + SGI_OFF);    // [2][3][32][16] fp16
    float* sRed = (float*)(smc + SRED_OFF);    // [4][32][52]
    const uint32_t sWu = smem_u32(sW);
    const uint32_t sAu = smem_u32(sA);

    const int tid  = threadIdx.x;
    const int lane = tid & 31;
    const int wid  = tid >> 5;
    const int ji   = blockIdx.x & 31;
    const int bi   = blockIdx.x >> 5;
    const int jbase = ji * 16;
    const int bbase = bi * 32;
    const int eb = tid & 31;
    const int jq = tid >> 5;

    // stage weights once: 48 rows of 1024B
    for (int p = tid; p < 48 * 64; p += SCAN_THREADS) {
        int row = p >> 6, seg = p & 63;
        int gc = (row % 3) * HH + jbase + row / 3;   // c = jl*3+g -> gc
        cp16(sW + row * WROWB + seg * 16, g_Whf + (size_t)gc * 512 + seg * 8);
    }
    // prefetch gi for t=0 into buffer 0 (192 x 16B segs, fp16)
#pragma unroll
    for (int q = 0; q < 2; ++q) {
        int p = tid + q * SCAN_THREADS;
        if (p < 192) {
            int g = p / 64, rem = p % 64;
            int b = rem >> 1, half16 = rem & 1;
            cp16(sGI + (g * 32 + b) * 16 + half16 * 8,
                 g_GI + (size_t)(bbase + b) * H3 + g * HH + jbase + half16 * 8);
        }
    }
    asm volatile("cp.async.commit_group;");
    asm volatile("cp.async.wait_group 0;");
    __syncthreads();                            // weights + gi(0) visible to all

    float bhn_j[4];
#pragma unroll
    for (int ii = 0; ii < 4; ++ii) bhn_j[ii] = bhn[jbase + jq * 4 + ii];

    const int lrow = lane & 15;
    const int lcol8 = (lane >> 4) * 8;
    const float myScale = (wid < 2) ? 1.0f : 4.8828125e-4f;   // lo warps: 2^-11
    unsigned int gen = 0;

    for (int t = 0; t < TT; ++t) {
        const __half* hsrc = g_Hf + (t & 1) * BB * 1024;
        __half* hdst       = g_Hf + ((t + 1) & 1) * BB * 1024;

        // per-warp staging: warp w stages ONLY its own 512B-wide k'-chunk.
        // One warp instruction = 32 lanes x 16B = 512B contiguous gmem.
        {
            const char* srcb = (const char*)hsrc + (size_t)bbase * 2048 + wid * 512;
            char* dstb = sA + wid * 512;
#pragma unroll
            for (int q = 0; q < 32; ++q)
                cp16(dstb + q * ROWB + lane * 16, srcb + (size_t)q * 2048 + lane * 16);
        }
        asm volatile("cp.async.commit_group;");
        asm volatile("cp.async.wait_group 0;");   // own h chunk + own gi-prefetch share

        // single fp16 pass, 4-way k'-split: warps 0,1 -> hi@Whi (scale 1),
        // warps 2,3 -> lo_s@Whi (scale 2^-11). Each warp reads ONLY its own chunk.
        float acc[2][6][4];
#pragma unroll
        for (int mt = 0; mt < 2; ++mt)
#pragma unroll
            for (int nt = 0; nt < 6; ++nt)
#pragma unroll
                for (int q = 0; q < 4; ++q) acc[mt][nt][q] = 0.f;

#pragma unroll
        for (int ks = 0; ks < 16; ++ks) {
            const int colA = wid * 256 + ks * 16 + lcol8;
            const int colB = ((wid & 1) ? 256 : 0) + ks * 16 + lcol8;
            uint32_t af[2][4];
#pragma unroll
            for (int mt = 0; mt < 2; ++mt)
                ldsm_x4(af[mt][0], af[mt][1], af[mt][2], af[mt][3],
                        sAu + (uint32_t)(mt * 16 + lrow) * ROWB + colA * 2);
            uint32_t bf[3][4];
#pragma unroll
            for (int ng = 0; ng < 3; ++ng)
                ldsm_x4(bf[ng][0], bf[ng][1], bf[ng][2], bf[ng][3],
                        sWu + (uint32_t)(ng * 16 + lrow) * WROWB + colB * 2);
#pragma unroll
            for (int mt = 0; mt < 2; ++mt)
#pragma unroll
                for (int ng = 0; ng < 3; ++ng) {
                    mma_f16(acc[mt][ng * 2 + 0], af[mt], bf[ng][0], bf[ng][2]);
                    mma_f16(acc[mt][ng * 2 + 1], af[mt], bf[ng][1], bf[ng][3]);
                }
        }

        // write per-warp partials to sRed[w][b][c] (lo warps pre-scaled)
        {
            const int bfr = lane >> 2;
            const int cfr = (lane & 3) * 2;
            float* rw = sRed + wid * (32 * 52);
#pragma unroll
            for (int mt = 0; mt < 2; ++mt)
#pragma unroll
                for (int nt = 0; nt < 6; ++nt) {
                    const int b0 = mt * 16 + bfr;
                    const int c0 = nt * 8 + cfr;
                    float2 v0, v1;
                    v0.x = acc[mt][nt][0] * myScale; v0.y = acc[mt][nt][1] * myScale;
                    v1.x = acc[mt][nt][2] * myScale; v1.y = acc[mt][nt][3] * myScale;
                    *(float2*)(rw + b0 * 52 + c0) = v0;
                    *(float2*)(rw + (b0 + 8) * 52 + c0) = v1;
                }
        }
        __syncthreads();   // cross-warp: sRed + all warps' sA chunks visible

        // old-h for the z-blend (reads chunks staged by other warps -> post-sync)
        float hv[4];
        {
            const __half* sAb = (const __half*)sA;
#pragma unroll
            for (int ii = 0; ii < 4; ++ii) {
                const int jg = jbase + jq * 4 + ii;
                float hi = __half2float(sAb[eb * 1032 + jg]);
                float lo = __half2float(sAb[eb * 1032 + 512 + jg]);
                hv[ii] = hi + lo * 4.8828125e-4f;
            }
        }

        // epilogue: thread handles (b = bbase+eb, j = jbase + jq*4 + ii)
        const __half* gib = sGI + (t & 1) * 1536;
        const float rs = g_RS[(t + 1) * BB + bbase + eb];
        float nhv[4];
#pragma unroll
        for (int ii = 0; ii < 4; ++ii) {
            const int cb = (jq * 4 + ii) * 3;
            float aR = 0.f, aZ = 0.f, aN = 0.f;
#pragma unroll
            for (int w = 0; w < 4; ++w) {
                const float* p = sRed + w * (32 * 52) + eb * 52 + cb;
                aR += p[0]; aZ += p[1]; aN += p[2];
            }
            const int jl = jq * 4 + ii;
            const float gir = __half2float(gib[(0 * 32 + eb) * 16 + jl]);
            const float giz = __half2float(gib[(1 * 32 + eb) * 16 + jl]);
            const float gin = __half2float(gib[(2 * 32 + eb) * 16 + jl]);
            const float rr = fsigmoid(aR + gir);
            const float zz = fsigmoid(aZ + giz);
            const float nn = ftanh_fast(gin + rr * (aN + bhn_j[ii]));
            nhv[ii] = (1.f - zz) * nn + zz * hv[ii];
        }
        float4 nh4;
        nh4.x = nhv[0]; nh4.y = nhv[1]; nh4.z = nhv[2]; nh4.w = nhv[3];
        *(float4*)(out + ((size_t)t * BB + bbase + eb) * HH + jbase + jq * 4) = nh4;

        // store next h (reset folded) as fp16 hi/lo_s, row-major [b][hi|lo]
        {
            union { __half b[4]; unsigned long long u; } phi, plo;
#pragma unroll
            for (int ii = 0; ii < 4; ++ii) {
                float hn = nhv[ii] * rs;
                __half hi = __float2half(hn);
                __half lo = __float2half((hn - __half2float(hi)) * 2048.0f);
                phi.b[ii] = hi; plo.b[ii] = lo;
            }
            const size_t rowb = (size_t)(bbase + eb) * 1024 + jbase + jq * 4;
            *(unsigned long long*)(hdst + rowb) = phi.u;
            *(unsigned long long*)(hdst + rowb + 512) = plo.u;
        }

        // prefetch gi for step t+1 (fp16, 192 x 16B segs)
        {
            const int tn = (t + 1 < TT) ? (t + 1) : (TT - 1);
            __half* gin_dst = sGI + ((t + 1) & 1) * 1536;
            const __half* gin_src = g_GI + (size_t)tn * BB * H3;
#pragma unroll
            for (int q = 0; q < 2; ++q) {
                int p = tid + q * SCAN_THREADS;
                if (p < 192) {
                    int g = p / 64, rem = p % 64;
                    int b = rem >> 1, half16 = rem & 1;
                    cp16(gin_dst + (g * 32 + b) * 16 + half16 * 8,
                         gin_src + (size_t)(bbase + b) * H3 + g * HH + jbase + half16 * 8);
                }
            }
            asm volatile("cp.async.commit_group;");
        }

        group_sync(bi, gen);
    }
}

// ---------------- launch ----------------
extern "C" void kernel_launch(void* const* d_in, const int* in_sizes, int n_in,
                              void* d_out, int out_size) {
    const float* x    = (const float*)d_in[0];   // [T,B,H]
    const void*  rst  = d_in[1];                 // [T,B] bool (unknown storage)
    const float* Wi   = (const float*)d_in[2];   // [H,3H]
    const float* bi   = (const float*)d_in[3];   // [3H]
    const float* Wh   = (const float*)d_in[4];   // [H,3H]
    const float* bhn  = (const float*)d_in[5];   // [H]
    const float* h0   = (const float*)d_in[6];   // [B,H]
    float* out = (float*)d_out;

    (void)in_sizes; (void)n_in; (void)out_size;

    detect_reset_mode_kernel<<<1, 256>>>((const unsigned char*)rst);
    expand_resets_kernel<<<((TT + 1) * BB + 255) / 256, 256>>>(rst);
    init_kernel<<<(BB * HH + 255) / 256, 256>>>(h0);

    // fp16 operand builds
    convert_x_kernel<<<2048, 256>>>(x);
    convert_w_kernel<<<1024, 256>>>(Wi);
    convert_wh_kernel<<<1024, 256>>>(Wh);

    // GI = x @ Wi + bi via HMMA fp16 (split-K' = 1024), fp16 output
    cudaFuncSetAttribute(gi_hmma_kernel,
                         cudaFuncAttributeMaxDynamicSharedMemorySize, HB_SMEM_BYTES);
    gi_hmma_kernel<<<6144, 256, HB_SMEM_BYTES>>>(bi);

    // persistent sequential scan (h@Wh on tensor pipe, per-warp staging)
    cudaFuncSetAttribute(scan_kernel,
                         cudaFuncAttributeMaxDynamicSharedMemorySize, SCAN_SMEM_BYTES);
    scan_kernel<<<NCTA, SCAN_THREADS, SCAN_SMEM_BYTES>>>(bhn, out);
}